// round 7
// baseline (speedup 1.0000x reference)
#include <cuda_runtime.h>
#include <cuda_fp16.h>
#include <cstdint>
#include <cstddef>

#define NN   100000
#define IND  512
#define HIDD 256
#define OUTD 64
#define NEDGE_MAX 3400000

// Scratch (device globals: allocation-free, graph-capture safe). ~210 MB.
__device__ __half g_sup1[(size_t)NN * HIDD]; // x @ W1  (fp16 storage, fp32 math)
__device__ float  g_h   [(size_t)NN * HIDD]; // spmm1 result
__device__ float  g_sup2[(size_t)NN * OUTD]; // relu(h) @ W2
__device__ int    g_deg   [NN];
__device__ int    g_rowptr[NN + 1];
__device__ int    g_cursor[NN];
__device__ int2   g_csr   [NEDGE_MAX];       // {src, w-bits} sorted by dst

__device__ __forceinline__ float to_tf32(float x) {
    float r;
    asm("cvt.rna.tf32.f32 %0, %1;" : "=f"(r) : "f"(x));
    return r;
}

// ---------------------------------------------------------------------------
// TF32 tensor-core GEMM, double-buffered SMEM + register prefetch.
// C[M,N] = A[M,K] @ B[K,N], row-major. BM=128, BK=32, 512 threads = 16 warps
// (4M x 4N), warp tile 32 x (BN/4), mma.m16n8k8.tf32, one sync per K-iter.
// ---------------------------------------------------------------------------
template <int BN, bool RELU, bool HALF_OUT>
__global__ __launch_bounds__(512) void gemm_tf32_db(const float* __restrict__ A,
                                                    const float* __restrict__ B,
                                                    void* __restrict__ Cv,
                                                    int M, int N, int K) {
    constexpr int BM = 128, BK = 32;
    constexpr int PA = BK + 4;                  // 36 floats: conflict-free
    constexpr int PB = BN + 8;                  // (BN+8) mod 32 == 8: conflict-free
    constexpr int WN = BN / 4;
    constexpr int NT = WN / 8;
    constexpr int B_LD = (BK * BN) / (4 * 512); // float4 per thread (2 or 1)

    extern __shared__ float sm[];
    float* As = sm;                  // [2][BM][PA]
    float* Bs = sm + 2 * BM * PA;    // [2][BK][PB]

    const int tid  = threadIdx.x;
    const int warp = tid >> 5;
    const int lane = tid & 31;
    const int g    = lane >> 2;
    const int t    = lane & 3;
    const int wm   = warp & 3;
    const int wn   = warp >> 2;
    const int bm   = blockIdx.y * BM;
    const int bn   = blockIdx.x * BN;

    float acc[2][NT][4];
#pragma unroll
    for (int mt = 0; mt < 2; mt++)
#pragma unroll
        for (int nt = 0; nt < NT; nt++)
#pragma unroll
            for (int i = 0; i < 4; i++) acc[mt][nt][i] = 0.f;

    float4 pa[2];
    float4 pb[B_LD];

    auto loadA = [&](int k0) {
#pragma unroll
        for (int i = 0; i < 2; i++) {
            int idx = tid + i * 512;
            int r   = idx >> 3;
            int c4  = idx & 7;
            int gr  = bm + r;
            float4 v = make_float4(0.f, 0.f, 0.f, 0.f);
            if (gr < M) v = *(const float4*)(A + (size_t)gr * K + k0 + c4 * 4);
            if (RELU) {
                v.x = fmaxf(v.x, 0.f); v.y = fmaxf(v.y, 0.f);
                v.z = fmaxf(v.z, 0.f); v.w = fmaxf(v.w, 0.f);
            }
            pa[i] = v;
        }
    };
    auto loadB = [&](int k0) {
#pragma unroll
        for (int i = 0; i < B_LD; i++) {
            int idx = tid + i * 512;
            int r   = idx / (BN / 4);
            int c4  = idx % (BN / 4);
            pb[i] = *(const float4*)(B + (size_t)(k0 + r) * N + bn + c4 * 4);
        }
    };
    auto storeTiles = [&](int buf) {
#pragma unroll
        for (int i = 0; i < 2; i++) {
            int idx = tid + i * 512;
            int r   = idx >> 3;
            int c4  = idx & 7;
            float4 v = pa[i];
            v.x = to_tf32(v.x); v.y = to_tf32(v.y);
            v.z = to_tf32(v.z); v.w = to_tf32(v.w);
            *(float4*)&As[(buf * BM + r) * PA + c4 * 4] = v;
        }
#pragma unroll
        for (int i = 0; i < B_LD; i++) {
            int idx = tid + i * 512;
            int r   = idx / (BN / 4);
            int c4  = idx % (BN / 4);
            float4 v = pb[i];
            v.x = to_tf32(v.x); v.y = to_tf32(v.y);
            v.z = to_tf32(v.z); v.w = to_tf32(v.w);
            *(float4*)&Bs[(buf * BK + r) * PB + c4 * 4] = v;
        }
    };
    auto doMMA = [&](int buf) {
        const float* Ab = &As[buf * BM * PA];
        const float* Bb = &Bs[buf * BK * PB];
#pragma unroll
        for (int kk = 0; kk < 4; kk++) {
            unsigned a[2][4], b[NT][2];
#pragma unroll
            for (int mt = 0; mt < 2; mt++) {
                int row = wm * 32 + mt * 16 + g;
                a[mt][0] = __float_as_uint(Ab[ row      * PA + kk * 8 + t    ]);
                a[mt][1] = __float_as_uint(Ab[(row + 8) * PA + kk * 8 + t    ]);
                a[mt][2] = __float_as_uint(Ab[ row      * PA + kk * 8 + t + 4]);
                a[mt][3] = __float_as_uint(Ab[(row + 8) * PA + kk * 8 + t + 4]);
            }
#pragma unroll
            for (int nt = 0; nt < NT; nt++) {
                int col = wn * WN + nt * 8 + g;
                b[nt][0] = __float_as_uint(Bb[(kk * 8 + t    ) * PB + col]);
                b[nt][1] = __float_as_uint(Bb[(kk * 8 + t + 4) * PB + col]);
            }
#pragma unroll
            for (int mt = 0; mt < 2; mt++)
#pragma unroll
                for (int nt = 0; nt < NT; nt++) {
                    asm volatile(
                        "mma.sync.aligned.m16n8k8.row.col.f32.tf32.tf32.f32 "
                        "{%0,%1,%2,%3}, {%4,%5,%6,%7}, {%8,%9}, {%0,%1,%2,%3};"
                        : "+f"(acc[mt][nt][0]), "+f"(acc[mt][nt][1]),
                          "+f"(acc[mt][nt][2]), "+f"(acc[mt][nt][3])
                        : "r"(a[mt][0]), "r"(a[mt][1]), "r"(a[mt][2]), "r"(a[mt][3]),
                          "r"(b[nt][0]), "r"(b[nt][1]));
                }
        }
    };

    // Prologue: fill buffer 0.
    loadA(0); loadB(0);
    storeTiles(0);
    __syncthreads();

    int buf = 0;
    for (int k0 = 0; k0 < K; k0 += BK) {
        int kn = k0 + BK;
        if (kn < K) { loadA(kn); loadB(kn); }     // prefetch into registers
        doMMA(buf);                                // consume current buffer
        if (kn < K) {
            storeTiles(buf ^ 1);                   // fill the other buffer
            __syncthreads();
            buf ^= 1;
        }
    }

    // Epilogue.
#pragma unroll
    for (int mt = 0; mt < 2; mt++) {
        int row0 = bm + wm * 32 + mt * 16 + g;
#pragma unroll
        for (int nt = 0; nt < NT; nt++) {
            int col = bn + wn * WN + nt * 8 + t * 2;
            if (HALF_OUT) {
                __half* C = (__half*)Cv;
                if (row0 < M)
                    *(__half2*)(C + (size_t)row0 * N + col) =
                        __floats2half2_rn(acc[mt][nt][0], acc[mt][nt][1]);
                if (row0 + 8 < M)
                    *(__half2*)(C + (size_t)(row0 + 8) * N + col) =
                        __floats2half2_rn(acc[mt][nt][2], acc[mt][nt][3]);
            } else {
                float* C = (float*)Cv;
                if (row0 < M)
                    *(float2*)(C + (size_t)row0 * N + col) =
                        make_float2(acc[mt][nt][0], acc[mt][nt][1]);
                if (row0 + 8 < M)
                    *(float2*)(C + (size_t)(row0 + 8) * N + col) =
                        make_float2(acc[mt][nt][2], acc[mt][nt][3]);
            }
        }
    }
}

// ---------------------------------------------------------------------------
// CSR build: memset -> histogram(4/thr) -> single-block scan -> scatter(4/thr)
// ---------------------------------------------------------------------------
__global__ __launch_bounds__(256) void hist_dst(const int* __restrict__ dst,
                                                int* __restrict__ deg, int E) {
    int i = (blockIdx.x * 256 + threadIdx.x) * 4;
    if (i + 4 <= E) {
        int4 d = *(const int4*)(dst + i);
        atomicAdd(&deg[d.x], 1);
        atomicAdd(&deg[d.y], 1);
        atomicAdd(&deg[d.z], 1);
        atomicAdd(&deg[d.w], 1);
    } else {
        for (; i < E; i++) atomicAdd(&deg[dst[i]], 1);
    }
}

__global__ __launch_bounds__(1024) void scan_deg(const int* __restrict__ deg,
                                                 int* __restrict__ rowptr,
                                                 int* __restrict__ cursor, int n) {
    __shared__ int warp_sums[32];
    const int tid  = threadIdx.x;
    const int lane = tid & 31;
    const int wid  = tid >> 5;
    const int per  = (n + 1023) / 1024;
    const int start = tid * per;
    const int end   = min(start + per, n);

    int sum = 0;
    for (int i = start; i < end; i++) sum += deg[i];

    int v = sum;
#pragma unroll
    for (int o = 1; o < 32; o <<= 1) {
        int u = __shfl_up_sync(0xFFFFFFFFu, v, o);
        if (lane >= o) v += u;
    }
    if (lane == 31) warp_sums[wid] = v;
    __syncthreads();
    if (wid == 0) {
        int s = warp_sums[lane];
#pragma unroll
        for (int o = 1; o < 32; o <<= 1) {
            int u = __shfl_up_sync(0xFFFFFFFFu, s, o);
            if (lane >= o) s += u;
        }
        warp_sums[lane] = s;
    }
    __syncthreads();

    int run = v - sum + (wid ? warp_sums[wid - 1] : 0);
    for (int i = start; i < end; i++) {
        rowptr[i] = run;
        cursor[i] = run;
        run += deg[i];
    }
    if (start < n && end == n) rowptr[n] = run;
}

__global__ __launch_bounds__(256) void scatter_edges(const int* __restrict__ src,
                                                     const int* __restrict__ dst,
                                                     const float* __restrict__ w,
                                                     int* __restrict__ cursor,
                                                     int2* __restrict__ csr, int E) {
    int i = (blockIdx.x * 256 + threadIdx.x) * 4;
    if (i + 4 <= E) {
        int4   s4 = *(const int4*)(src + i);
        int4   d4 = *(const int4*)(dst + i);
        float4 w4 = *(const float4*)(w + i);
        int p0 = atomicAdd(&cursor[d4.x], 1);
        int p1 = atomicAdd(&cursor[d4.y], 1);
        int p2 = atomicAdd(&cursor[d4.z], 1);
        int p3 = atomicAdd(&cursor[d4.w], 1);
        csr[p0] = make_int2(s4.x, __float_as_int(w4.x));
        csr[p1] = make_int2(s4.y, __float_as_int(w4.y));
        csr[p2] = make_int2(s4.z, __float_as_int(w4.z));
        csr[p3] = make_int2(s4.w, __float_as_int(w4.w));
    } else {
        for (; i < E; i++) {
            int pos = atomicAdd(&cursor[dst[i]], 1);
            csr[pos] = make_int2(src[i], __float_as_int(w[i]));
        }
    }
}

// ---------------------------------------------------------------------------
// CSR SpMM, F=256, fp16 gather / fp32 accum: one warp per dst row, 4-edge MLP.
// ---------------------------------------------------------------------------
__global__ __launch_bounds__(256) void spmm_csr_f256h(const int* __restrict__ rowptr,
                                                      const int2* __restrict__ csr,
                                                      const __half* __restrict__ sup,
                                                      float* __restrict__ out, int n) {
    int row  = (blockIdx.x * 256 + threadIdx.x) >> 5;
    int lane = threadIdx.x & 31;
    if (row >= n) return;
    int e   = rowptr[row];
    int end = rowptr[row + 1];

    float acc[8];
#pragma unroll
    for (int i = 0; i < 8; i++) acc[i] = 0.f;

    for (; e + 4 <= end; e += 4) {
        int2 sw0 = __ldg(&csr[e]);
        int2 sw1 = __ldg(&csr[e + 1]);
        int2 sw2 = __ldg(&csr[e + 2]);
        int2 sw3 = __ldg(&csr[e + 3]);
        uint4 v0 = ((const uint4*)(sup + (size_t)sw0.x * 256))[lane];
        uint4 v1 = ((const uint4*)(sup + (size_t)sw1.x * 256))[lane];
        uint4 v2 = ((const uint4*)(sup + (size_t)sw2.x * 256))[lane];
        uint4 v3 = ((const uint4*)(sup + (size_t)sw3.x * 256))[lane];
        float w0 = __int_as_float(sw0.y);
        float w1 = __int_as_float(sw1.y);
        float w2 = __int_as_float(sw2.y);
        float w3 = __int_as_float(sw3.y);
        const __half2* h0 = (const __half2*)&v0;
        const __half2* h1 = (const __half2*)&v1;
        const __half2* h2 = (const __half2*)&v2;
        const __half2* h3 = (const __half2*)&v3;
#pragma unroll
        for (int j = 0; j < 4; j++) {
            float2 f0 = __half22float2(h0[j]);
            float2 f1 = __half22float2(h1[j]);
            float2 f2 = __half22float2(h2[j]);
            float2 f3 = __half22float2(h3[j]);
            acc[2 * j]     += w0 * f0.x + w1 * f1.x + w2 * f2.x + w3 * f3.x;
            acc[2 * j + 1] += w0 * f0.y + w1 * f1.y + w2 * f2.y + w3 * f3.y;
        }
    }
    for (; e < end; e++) {
        int2 sw = __ldg(&csr[e]);
        float w = __int_as_float(sw.y);
        uint4 v = ((const uint4*)(sup + (size_t)sw.x * 256))[lane];
        const __half2* h = (const __half2*)&v;
#pragma unroll
        for (int j = 0; j < 4; j++) {
            float2 f = __half22float2(h[j]);
            acc[2 * j]     += w * f.x;
            acc[2 * j + 1] += w * f.y;
        }
    }

    float4* orow = (float4*)(out + (size_t)row * 256 + lane * 8);
    orow[0] = make_float4(acc[0], acc[1], acc[2], acc[3]);
    orow[1] = make_float4(acc[4], acc[5], acc[6], acc[7]);
}

// ---------------------------------------------------------------------------
// CSR SpMM, F=64 (fp32), fused row-softmax: one warp per dst row, 4-edge MLP.
// ---------------------------------------------------------------------------
__global__ __launch_bounds__(256) void spmm_csr_f64_softmax(const int* __restrict__ rowptr,
                                                            const int2* __restrict__ csr,
                                                            const float* __restrict__ sup,
                                                            float* __restrict__ out, int n) {
    int row  = (blockIdx.x * 256 + threadIdx.x) >> 5;
    int lane = threadIdx.x & 31;
    if (row >= n) return;
    int e   = rowptr[row];
    int end = rowptr[row + 1];

    float2 acc = make_float2(0.f, 0.f);

    for (; e + 4 <= end; e += 4) {
        int2 sw0 = __ldg(&csr[e]);
        int2 sw1 = __ldg(&csr[e + 1]);
        int2 sw2 = __ldg(&csr[e + 2]);
        int2 sw3 = __ldg(&csr[e + 3]);
        float2 v0 = ((const float2*)(sup + (size_t)sw0.x * 64))[lane];
        float2 v1 = ((const float2*)(sup + (size_t)sw1.x * 64))[lane];
        float2 v2 = ((const float2*)(sup + (size_t)sw2.x * 64))[lane];
        float2 v3 = ((const float2*)(sup + (size_t)sw3.x * 64))[lane];
        float w0 = __int_as_float(sw0.y);
        float w1 = __int_as_float(sw1.y);
        float w2 = __int_as_float(sw2.y);
        float w3 = __int_as_float(sw3.y);
        acc.x += w0 * v0.x + w1 * v1.x + w2 * v2.x + w3 * v3.x;
        acc.y += w0 * v0.y + w1 * v1.y + w2 * v2.y + w3 * v3.y;
    }
    for (; e < end; e++) {
        int2 sw = __ldg(&csr[e]);
        float w = __int_as_float(sw.y);
        float2 v = ((const float2*)(sup + (size_t)sw.x * 64))[lane];
        acc.x += w * v.x;
        acc.y += w * v.y;
    }

    float m = fmaxf(acc.x, acc.y);
#pragma unroll
    for (int o = 16; o; o >>= 1) m = fmaxf(m, __shfl_xor_sync(0xFFFFFFFFu, m, o));
    float ex = __expf(acc.x - m);
    float ey = __expf(acc.y - m);
    float s  = ex + ey;
#pragma unroll
    for (int o = 16; o; o >>= 1) s += __shfl_xor_sync(0xFFFFFFFFu, s, o);
    float inv = 1.f / s;
    ((float2*)(out + (size_t)row * 64))[lane] = make_float2(ex * inv, ey * inv);
}

// ---------------------------------------------------------------------------
extern "C" void kernel_launch(void* const* d_in, const int* in_sizes, int n_in,
                              void* d_out, int out_size) {
    const float* x  = (const float*)d_in[0];
    const int*   ei = (const int*)d_in[1];
    const float* ew = (const float*)d_in[2];
    const float* W1 = (const float*)d_in[3];
    const float* W2 = (const float*)d_in[4];
    float*       out = (float*)d_out;

    const int E = in_sizes[2];
    const int M = in_sizes[0] / IND;
    const int* src = ei;
    const int* dst = ei + E;

    __half* p_sup1;
    float *p_h, *p_sup2;
    int *p_deg, *p_rowptr, *p_cursor;
    int2 *p_csr;
    cudaGetSymbolAddress((void**)&p_sup1,   g_sup1);
    cudaGetSymbolAddress((void**)&p_h,      g_h);
    cudaGetSymbolAddress((void**)&p_sup2,   g_sup2);
    cudaGetSymbolAddress((void**)&p_deg,    g_deg);
    cudaGetSymbolAddress((void**)&p_rowptr, g_rowptr);
    cudaGetSymbolAddress((void**)&p_cursor, g_cursor);
    cudaGetSymbolAddress((void**)&p_csr,    g_csr);

    const int mt128 = (M + 127) / 128;

    // Dynamic SMEM: double-buffered tiles exceed the 48 KB static limit.
    const int smem1 = (2 * 128 * 36 + 2 * 32 * (128 + 8)) * 4;  // 71680 B
    const int smem2 = (2 * 128 * 36 + 2 * 32 * (64 + 8)) * 4;   // 55296 B
    cudaFuncSetAttribute(gemm_tf32_db<128, false, true>,
                         cudaFuncAttributeMaxDynamicSharedMemorySize, smem1);
    cudaFuncSetAttribute(gemm_tf32_db<64, true, false>,
                         cudaFuncAttributeMaxDynamicSharedMemorySize, smem2);

    // CSR build (dst-sorted adjacency, reused by both layers)
    cudaMemsetAsync(p_deg, 0, (size_t)M * sizeof(int));
    hist_dst<<<(E / 4 + 255) / 256, 256>>>(dst, p_deg, E);
    scan_deg<<<1, 1024>>>(p_deg, p_rowptr, p_cursor, M);
    scatter_edges<<<(E / 4 + 255) / 256, 256>>>(src, dst, ew, p_cursor, p_csr, E);

    // Layer 1: sup1 = fp16(x @ W1) ; h = A @ sup1
    gemm_tf32_db<128, false, true><<<dim3(HIDD / 128, mt128), 512, smem1>>>(
        x, W1, p_sup1, M, HIDD, IND);
    spmm_csr_f256h<<<(M * 32 + 255) / 256, 256>>>(p_rowptr, p_csr, p_sup1, p_h, M);

    // Layer 2: sup2 = relu(h) @ W2 ; out = softmax(A @ sup2)
    gemm_tf32_db<64, true, false><<<dim3(OUTD / 64, mt128), 512, smem2>>>(
        p_h, W2, p_sup2, M, OUTD, HIDD);
    spmm_csr_f64_softmax<<<(M * 32 + 255) / 256, 256>>>(p_rowptr, p_csr, p_sup2, out, M);
}

// round 9
// speedup vs baseline: 1.0668x; 1.0668x over previous
#include <cuda_runtime.h>
#include <cuda_fp16.h>
#include <cstdint>
#include <cstddef>

#define NN   100000
#define IND  512
#define HIDD 256
#define OUTD 64
#define NEDGE_MAX 3400000

// Scratch (device globals: allocation-free, graph-capture safe). ~210 MB.
__device__ __half g_sup1[(size_t)NN * HIDD]; // x @ W1  (fp16 storage, fp32 math)
__device__ float  g_h   [(size_t)NN * HIDD]; // spmm1 result
__device__ float  g_sup2[(size_t)NN * OUTD]; // relu(h) @ W2
__device__ int    g_deg   [NN];
__device__ int    g_rowptr[NN + 1];
__device__ int    g_cursor[NN];
__device__ int2   g_csr   [NEDGE_MAX];       // {src, w-bits} sorted by dst

// Bit-cast half2 -> u32 (register move; __half2_as_uint doesn't exist).
__device__ __forceinline__ unsigned h2_as_u32(__half2 h) {
    unsigned u;
    *reinterpret_cast<__half2*>(&u) = h;
    return u;
}
__device__ __forceinline__ unsigned pack_h2(float lo, float hi) {
    return h2_as_u32(__floats2half2_rn(lo, hi));
}

// ---------------------------------------------------------------------------
// FP16 tensor-core GEMM (fp32 accumulate): C[M,N] = A[M,K] @ B[K,N], row-major
// fp32 inputs rounded to fp16 at SMEM fill (same 11-bit mantissa as TF32).
// BM=128, BK=32, 256 thr = 8 warps (4M x 2N), warp tile 32 x (BN/2),
// mma.sync.m16n8k16.f32.f16.f16.f32. SMEM holds half2 packed along K.
// ---------------------------------------------------------------------------
template <int BN, bool RELU, bool HALF_OUT>
__global__ __launch_bounds__(256) void gemm_f16(const float* __restrict__ A,
                                                const float* __restrict__ B,
                                                void* __restrict__ Cv,
                                                int M, int N, int K) {
    constexpr int BM = 128, BK = 32;
    constexpr int PA = 20;        // words per A row (16 half2 + 4 pad) -> conflict-free frags
    constexpr int PB = BN + 8;    // words per B k2-row -> conflict-free frags
    constexpr int WN = BN / 2;
    constexpr int NT = WN / 8;

    __shared__ __align__(16) unsigned As2[BM * PA];        // As2[r*PA+k2]=half2(A[r][2k2],A[r][2k2+1])
    __shared__ __align__(16) unsigned Bs2[(BK / 2) * PB];  // Bs2[k2*PB+n]=half2(B[2k2][n],B[2k2+1][n])

    const int tid  = threadIdx.x;
    const int warp = tid >> 5;
    const int lane = tid & 31;
    const int g    = lane >> 2;
    const int t    = lane & 3;
    const int wm   = warp & 3;
    const int wn   = warp >> 2;
    const int bm   = blockIdx.y * BM;
    const int bn   = blockIdx.x * BN;

    float acc[2][NT][4];
#pragma unroll
    for (int mt = 0; mt < 2; mt++)
#pragma unroll
        for (int nt = 0; nt < NT; nt++)
#pragma unroll
            for (int i = 0; i < 4; i++) acc[mt][nt][i] = 0.f;

    for (int k0 = 0; k0 < K; k0 += BK) {
        // ---- fill A tile: 1024 float4 reads -> STS.64 of 2 half2 each ----
#pragma unroll
        for (int i = 0; i < 4; i++) {
            int idx = tid + i * 256;
            int r   = idx >> 3;          // tile row 0..127
            int c4  = idx & 7;           // float4 index 0..7 (k = c4*4)
            int gr  = bm + r;
            float4 v = make_float4(0.f, 0.f, 0.f, 0.f);
            if (gr < M) v = *(const float4*)(A + (size_t)gr * K + k0 + c4 * 4);
            if (RELU) {
                v.x = fmaxf(v.x, 0.f); v.y = fmaxf(v.y, 0.f);
                v.z = fmaxf(v.z, 0.f); v.w = fmaxf(v.w, 0.f);
            }
            uint2 p;
            p.x = pack_h2(v.x, v.y);
            p.y = pack_h2(v.z, v.w);
            *(uint2*)&As2[r * PA + c4 * 2] = p;
        }
        // ---- fill B tile: items = (BK/2) x (BN/4); 2 float4 reads -> STS.128 ----
#pragma unroll
        for (int i = 0; i < (16 * BN / 4) / 256; i++) {
            int idx = tid + i * 256;
            int k2  = idx / (BN / 4);    // 0..15
            int n4  = idx % (BN / 4);    // float4 group along n
            const float* b0 = B + (size_t)(k0 + 2 * k2) * N + bn + n4 * 4;
            float4 r0 = *(const float4*)b0;
            float4 r1 = *(const float4*)(b0 + N);
            uint4 p;
            p.x = pack_h2(r0.x, r1.x);
            p.y = pack_h2(r0.y, r1.y);
            p.z = pack_h2(r0.z, r1.z);
            p.w = pack_h2(r0.w, r1.w);
            *(uint4*)&Bs2[k2 * PB + n4 * 4] = p;
        }
        __syncthreads();

#pragma unroll
        for (int kk = 0; kk < 2; kk++) {           // two k=16 steps
            unsigned a[2][4], b[NT][2];
#pragma unroll
            for (int mt = 0; mt < 2; mt++) {
                int row = wm * 32 + mt * 16 + g;
                int kb  = kk * 8 + t;
                a[mt][0] = As2[ row      * PA + kb    ];
                a[mt][1] = As2[(row + 8) * PA + kb    ];
                a[mt][2] = As2[ row      * PA + kb + 4];
                a[mt][3] = As2[(row + 8) * PA + kb + 4];
            }
#pragma unroll
            for (int nt = 0; nt < NT; nt++) {
                int col = wn * WN + nt * 8 + g;
                int kb  = kk * 8 + t;
                b[nt][0] = Bs2[ kb      * PB + col];
                b[nt][1] = Bs2[(kb + 4) * PB + col];
            }
#pragma unroll
            for (int mt = 0; mt < 2; mt++)
#pragma unroll
                for (int nt = 0; nt < NT; nt++) {
                    asm volatile(
                        "mma.sync.aligned.m16n8k16.row.col.f32.f16.f16.f32 "
                        "{%0,%1,%2,%3}, {%4,%5,%6,%7}, {%8,%9}, {%0,%1,%2,%3};"
                        : "+f"(acc[mt][nt][0]), "+f"(acc[mt][nt][1]),
                          "+f"(acc[mt][nt][2]), "+f"(acc[mt][nt][3])
                        : "r"(a[mt][0]), "r"(a[mt][1]), "r"(a[mt][2]), "r"(a[mt][3]),
                          "r"(b[nt][0]), "r"(b[nt][1]));
                }
        }
        __syncthreads();
    }

#pragma unroll
    for (int mt = 0; mt < 2; mt++) {
        int row0 = bm + wm * 32 + mt * 16 + g;
#pragma unroll
        for (int nt = 0; nt < NT; nt++) {
            int col = bn + wn * WN + nt * 8 + t * 2;
            if (HALF_OUT) {
                __half* C = (__half*)Cv;
                if (row0 < M)
                    *(__half2*)(C + (size_t)row0 * N + col) =
                        __floats2half2_rn(acc[mt][nt][0], acc[mt][nt][1]);
                if (row0 + 8 < M)
                    *(__half2*)(C + (size_t)(row0 + 8) * N + col) =
                        __floats2half2_rn(acc[mt][nt][2], acc[mt][nt][3]);
            } else {
                float* C = (float*)Cv;
                if (row0 < M)
                    *(float2*)(C + (size_t)row0 * N + col) =
                        make_float2(acc[mt][nt][0], acc[mt][nt][1]);
                if (row0 + 8 < M)
                    *(float2*)(C + (size_t)(row0 + 8) * N + col) =
                        make_float2(acc[mt][nt][2], acc[mt][nt][3]);
            }
        }
    }
}

// ---------------------------------------------------------------------------
// CSR build: memset -> histogram(4/thr) -> single-block scan -> scatter(2/thr)
// ---------------------------------------------------------------------------
__global__ __launch_bounds__(256) void hist_dst(const int* __restrict__ dst,
                                                int* __restrict__ deg, int E) {
    int i = (blockIdx.x * 256 + threadIdx.x) * 4;
    if (i + 4 <= E) {
        int4 d = *(const int4*)(dst + i);
        atomicAdd(&deg[d.x], 1);
        atomicAdd(&deg[d.y], 1);
        atomicAdd(&deg[d.z], 1);
        atomicAdd(&deg[d.w], 1);
    } else {
        for (; i < E; i++) atomicAdd(&deg[dst[i]], 1);
    }
}

__global__ __launch_bounds__(1024) void scan_deg(const int* __restrict__ deg,
                                                 int* __restrict__ rowptr,
                                                 int* __restrict__ cursor, int n) {
    __shared__ int warp_sums[32];
    const int tid  = threadIdx.x;
    const int lane = tid & 31;
    const int wid  = tid >> 5;
    const int per  = (n + 1023) / 1024;
    const int start = tid * per;
    const int end   = min(start + per, n);

    int sum = 0;
    for (int i = start; i < end; i++) sum += deg[i];

    int v = sum;
#pragma unroll
    for (int o = 1; o < 32; o <<= 1) {
        int u = __shfl_up_sync(0xFFFFFFFFu, v, o);
        if (lane >= o) v += u;
    }
    if (lane == 31) warp_sums[wid] = v;
    __syncthreads();
    if (wid == 0) {
        int s = warp_sums[lane];
#pragma unroll
        for (int o = 1; o < 32; o <<= 1) {
            int u = __shfl_up_sync(0xFFFFFFFFu, s, o);
            if (lane >= o) s += u;
        }
        warp_sums[lane] = s;
    }
    __syncthreads();

    int run = v - sum + (wid ? warp_sums[wid - 1] : 0);
    for (int i = start; i < end; i++) {
        rowptr[i] = run;
        cursor[i] = run;
        run += deg[i];
    }
    if (start < n && end == n) rowptr[n] = run;
}

__global__ __launch_bounds__(256) void scatter_edges(const int* __restrict__ src,
                                                     const int* __restrict__ dst,
                                                     const float* __restrict__ w,
                                                     int* __restrict__ cursor,
                                                     int2* __restrict__ csr, int E) {
    int i = (blockIdx.x * 256 + threadIdx.x) * 2;
    if (i + 2 <= E) {
        int2   s2 = *(const int2*)(src + i);
        int2   d2 = *(const int2*)(dst + i);
        float2 w2 = *(const float2*)(w + i);
        int p0 = atomicAdd(&cursor[d2.x], 1);
        int p1 = atomicAdd(&cursor[d2.y], 1);
        csr[p0] = make_int2(s2.x, __float_as_int(w2.x));
        csr[p1] = make_int2(s2.y, __float_as_int(w2.y));
    } else {
        for (; i < E; i++) {
            int pos = atomicAdd(&cursor[dst[i]], 1);
            csr[pos] = make_int2(src[i], __float_as_int(w[i]));
        }
    }
}

// ---------------------------------------------------------------------------
// CSR SpMM, F=256, fp16 gather / fp32 accum: one warp per dst row, 2-edge unroll.
// ---------------------------------------------------------------------------
__global__ __launch_bounds__(256) void spmm_csr_f256h(const int* __restrict__ rowptr,
                                                      const int2* __restrict__ csr,
                                                      const __half* __restrict__ sup,
                                                      float* __restrict__ out, int n) {
    int row  = (blockIdx.x * 256 + threadIdx.x) >> 5;
    int lane = threadIdx.x & 31;
    if (row >= n) return;
    int e   = rowptr[row];
    int end = rowptr[row + 1];

    float acc[8];
#pragma unroll
    for (int i = 0; i < 8; i++) acc[i] = 0.f;

    for (; e + 2 <= end; e += 2) {
        int2 sw0 = __ldg(&csr[e]);
        int2 sw1 = __ldg(&csr[e + 1]);
        float w0 = __int_as_float(sw0.y);
        float w1 = __int_as_float(sw1.y);
        uint4 v0 = ((const uint4*)(sup + (size_t)sw0.x * 256))[lane];
        uint4 v1 = ((const uint4*)(sup + (size_t)sw1.x * 256))[lane];
        const __half2* h0 = (const __half2*)&v0;
        const __half2* h1 = (const __half2*)&v1;
#pragma unroll
        for (int j = 0; j < 4; j++) {
            float2 f0 = __half22float2(h0[j]);
            float2 f1 = __half22float2(h1[j]);
            acc[2 * j]     += w0 * f0.x + w1 * f1.x;
            acc[2 * j + 1] += w0 * f0.y + w1 * f1.y;
        }
    }
    if (e < end) {
        int2 sw = __ldg(&csr[e]);
        float w = __int_as_float(sw.y);
        uint4 v = ((const uint4*)(sup + (size_t)sw.x * 256))[lane];
        const __half2* h = (const __half2*)&v;
#pragma unroll
        for (int j = 0; j < 4; j++) {
            float2 f = __half22float2(h[j]);
            acc[2 * j]     += w * f.x;
            acc[2 * j + 1] += w * f.y;
        }
    }

    float4* orow = (float4*)(out + (size_t)row * 256 + lane * 8);
    orow[0] = make_float4(acc[0], acc[1], acc[2], acc[3]);
    orow[1] = make_float4(acc[4], acc[5], acc[6], acc[7]);
}

// ---------------------------------------------------------------------------
// CSR SpMM, F=64 (fp32), fused row-softmax: one warp per dst row.
// ---------------------------------------------------------------------------
__global__ __launch_bounds__(256) void spmm_csr_f64_softmax(const int* __restrict__ rowptr,
                                                            const int2* __restrict__ csr,
                                                            const float* __restrict__ sup,
                                                            float* __restrict__ out, int n) {
    int row  = (blockIdx.x * 256 + threadIdx.x) >> 5;
    int lane = threadIdx.x & 31;
    if (row >= n) return;
    int e   = rowptr[row];
    int end = rowptr[row + 1];

    float2 acc = make_float2(0.f, 0.f);

    for (; e + 2 <= end; e += 2) {
        int2 sw0 = __ldg(&csr[e]);
        int2 sw1 = __ldg(&csr[e + 1]);
        float w0 = __int_as_float(sw0.y);
        float w1 = __int_as_float(sw1.y);
        float2 v0 = ((const float2*)(sup + (size_t)sw0.x * 64))[lane];
        float2 v1 = ((const float2*)(sup + (size_t)sw1.x * 64))[lane];
        acc.x += w0 * v0.x + w1 * v1.x;
        acc.y += w0 * v0.y + w1 * v1.y;
    }
    if (e < end) {
        int2 sw = __ldg(&csr[e]);
        float w = __int_as_float(sw.y);
        float2 v = ((const float2*)(sup + (size_t)sw.x * 64))[lane];
        acc.x += w * v.x;
        acc.y += w * v.y;
    }

    float m = fmaxf(acc.x, acc.y);
#pragma unroll
    for (int o = 16; o; o >>= 1) m = fmaxf(m, __shfl_xor_sync(0xFFFFFFFFu, m, o));
    float ex = __expf(acc.x - m);
    float ey = __expf(acc.y - m);
    float s  = ex + ey;
#pragma unroll
    for (int o = 16; o; o >>= 1) s += __shfl_xor_sync(0xFFFFFFFFu, s, o);
    float inv = 1.f / s;
    ((float2*)(out + (size_t)row * 64))[lane] = make_float2(ex * inv, ey * inv);
}

// ---------------------------------------------------------------------------
extern "C" void kernel_launch(void* const* d_in, const int* in_sizes, int n_in,
                              void* d_out, int out_size) {
    const float* x  = (const float*)d_in[0];
    const int*   ei = (const int*)d_in[1];
    const float* ew = (const float*)d_in[2];
    const float* W1 = (const float*)d_in[3];
    const float* W2 = (const float*)d_in[4];
    float*       out = (float*)d_out;

    const int E = in_sizes[2];
    const int M = in_sizes[0] / IND;
    const int* src = ei;
    const int* dst = ei + E;

    __half* p_sup1;
    float *p_h, *p_sup2;
    int *p_deg, *p_rowptr, *p_cursor;
    int2 *p_csr;
    cudaGetSymbolAddress((void**)&p_sup1,   g_sup1);
    cudaGetSymbolAddress((void**)&p_h,      g_h);
    cudaGetSymbolAddress((void**)&p_sup2,   g_sup2);
    cudaGetSymbolAddress((void**)&p_deg,    g_deg);
    cudaGetSymbolAddress((void**)&p_rowptr, g_rowptr);
    cudaGetSymbolAddress((void**)&p_cursor, g_cursor);
    cudaGetSymbolAddress((void**)&p_csr,    g_csr);

    const int mt128 = (M + 127) / 128;

    // CSR build (dst-sorted adjacency, reused by both layers)
    cudaMemsetAsync(p_deg, 0, (size_t)M * sizeof(int));
    hist_dst<<<(E / 4 + 255) / 256, 256>>>(dst, p_deg, E);
    scan_deg<<<1, 1024>>>(p_deg, p_rowptr, p_cursor, M);
    scatter_edges<<<(E / 2 + 255) / 256, 256>>>(src, dst, ew, p_cursor, p_csr, E);

    // Layer 1: sup1 = fp16(x @ W1) ; h = A @ sup1
    gemm_f16<128, false, true><<<dim3(HIDD / 128, mt128), 256>>>(x, W1, p_sup1, M, HIDD, IND);
    spmm_csr_f256h<<<(M * 32 + 255) / 256, 256>>>(p_rowptr, p_csr, p_sup1, p_h, M);

    // Layer 2: sup2 = relu(h) @ W2 ; out = softmax(A @ sup2)
    gemm_f16<64, true, false><<<dim3(OUTD / 64, mt128), 256>>>(p_h, W2, p_sup2, M, OUTD, HIDD);
    spmm_csr_f64_softmax<<<(M * 32 + 255) / 256, 256>>>(p_rowptr, p_csr, p_sup2, out, M);
}

// round 10
// speedup vs baseline: 1.2345x; 1.1572x over previous
#include <cuda_runtime.h>
#include <cuda_fp16.h>
#include <cstdint>
#include <cstddef>
#include <cstring>

#define NN   100000
#define IND  512
#define HIDD 256
#define OUTD 64
#define NEDGE_MAX 3400000

// Scratch (device globals: allocation-free, graph-capture safe). ~160 MB.
__device__ __half g_sup1[(size_t)NN * HIDD]; // fp16(x @ W1)
__device__ __half g_h   [(size_t)NN * HIDD]; // fp16(relu(spmm1))
__device__ float  g_sup2[(size_t)NN * OUTD]; // relu(h) @ W2
__device__ int    g_deg   [NN];
__device__ int    g_rowptr[NN + 1];
__device__ int    g_cursor[NN];
__device__ int2   g_csr   [NEDGE_MAX];       // {src, w-bits} sorted by dst

__device__ __forceinline__ unsigned h2_as_u32(__half2 h) {
    unsigned u;
    *reinterpret_cast<__half2*>(&u) = h;
    return u;
}
__device__ __forceinline__ unsigned pack_h2(float lo, float hi) {
    return h2_as_u32(__floats2half2_rn(lo, hi));
}

// ---------------------------------------------------------------------------
// FP16 tensor-core GEMM, double-buffered STATIC SMEM + register prefetch.
// C[M,N] = A[M,K] @ B[K,N] row-major; A fp32 (cvt at fill) or fp16 (A_HALF).
// BM=128, BK=32, 256 thr = 8 warps (4M x 2N), warp tile 32 x (BN/2),
// mma.sync.m16n8k16.f32.f16.f16.f32; one __syncthreads per K-iter.
// ---------------------------------------------------------------------------
template <int BN, bool A_HALF, bool HALF_OUT>
__global__ __launch_bounds__(256, 2) void gemm_f16_db(const void* __restrict__ Av,
                                                      const float* __restrict__ B,
                                                      void* __restrict__ Cv,
                                                      int M, int N, int K) {
    constexpr int BM = 128, BK = 32;
    constexpr int PA = 20;        // u32 words per A row (16 half2 + 4 pad)
    constexpr int PB = BN + 8;    // u32 words per B k2-row
    constexpr int WN = BN / 2;
    constexpr int NT = WN / 8;
    constexpr int BI = (16 * BN / 4) / 256;   // B fill items per thread (2 or 1)

    __shared__ __align__(16) unsigned As2[2][BM * PA];
    __shared__ __align__(16) unsigned Bs2[2][(BK / 2) * PB];

    const int tid  = threadIdx.x;
    const int warp = tid >> 5;
    const int lane = tid & 31;
    const int g    = lane >> 2;
    const int t    = lane & 3;
    const int wm   = warp & 3;
    const int wn   = warp >> 2;
    const int bm   = blockIdx.y * BM;
    const int bn   = blockIdx.x * BN;

    const float*  Af = (const float*)Av;
    const __half* Ah = (const __half*)Av;

    float acc[2][NT][4];
#pragma unroll
    for (int mt = 0; mt < 2; mt++)
#pragma unroll
        for (int nt = 0; nt < NT; nt++)
#pragma unroll
            for (int i = 0; i < 4; i++) acc[mt][nt][i] = 0.f;

    float4 pa[4];        // A prefetch (A_HALF uses pa[0..1] as uint4 bits)
    float4 pb[BI][2];    // B prefetch

    // ---- prefetch tile k0 into registers ----
    auto loadT = [&](int k0) {
        if (!A_HALF) {
#pragma unroll
            for (int i = 0; i < 4; i++) {
                int idx = tid + i * 256;
                int r   = idx >> 3;
                int c4  = idx & 7;
                int gr  = bm + r;
                float4 v = make_float4(0.f, 0.f, 0.f, 0.f);
                if (gr < M) v = *(const float4*)(Af + (size_t)gr * K + k0 + c4 * 4);
                pa[i] = v;
            }
        } else {
#pragma unroll
            for (int i = 0; i < 2; i++) {
                int idx = tid + i * 256;
                int r   = idx >> 2;
                int c   = idx & 3;       // uint4 (8 halves) within the 32-k row
                int gr  = bm + r;
                uint4 v = make_uint4(0u, 0u, 0u, 0u);
                if (gr < M) v = *(const uint4*)(Ah + (size_t)gr * K + k0 + c * 8);
                memcpy(&pa[i * 2], &v, 16);
            }
        }
#pragma unroll
        for (int i = 0; i < BI; i++) {
            int idx = tid + i * 256;
            int k2  = idx / (BN / 4);
            int n4  = idx % (BN / 4);
            const float* b0 = B + (size_t)(k0 + 2 * k2) * N + bn + n4 * 4;
            pb[i][0] = *(const float4*)b0;
            pb[i][1] = *(const float4*)(b0 + N);
        }
    };
    // ---- store prefetched registers into SMEM buffer `buf` ----
    auto storeT = [&](int buf) {
        if (!A_HALF) {
#pragma unroll
            for (int i = 0; i < 4; i++) {
                int idx = tid + i * 256;
                int r   = idx >> 3;
                int c4  = idx & 7;
                uint2 p;
                p.x = pack_h2(pa[i].x, pa[i].y);
                p.y = pack_h2(pa[i].z, pa[i].w);
                *(uint2*)&As2[buf][r * PA + c4 * 2] = p;
            }
        } else {
#pragma unroll
            for (int i = 0; i < 2; i++) {
                int idx = tid + i * 256;
                int r   = idx >> 2;
                int c   = idx & 3;
                uint4 v;
                memcpy(&v, &pa[i * 2], 16);
                *(uint4*)&As2[buf][r * PA + c * 4] = v;
            }
        }
#pragma unroll
        for (int i = 0; i < BI; i++) {
            int idx = tid + i * 256;
            int k2  = idx / (BN / 4);
            int n4  = idx % (BN / 4);
            uint4 p;
            p.x = pack_h2(pb[i][0].x, pb[i][1].x);
            p.y = pack_h2(pb[i][0].y, pb[i][1].y);
            p.z = pack_h2(pb[i][0].z, pb[i][1].z);
            p.w = pack_h2(pb[i][0].w, pb[i][1].w);
            *(uint4*)&Bs2[buf][k2 * PB + n4 * 4] = p;
        }
    };
    auto doMMA = [&](int buf) {
#pragma unroll
        for (int kk = 0; kk < 2; kk++) {
            unsigned a[2][4], b[NT][2];
#pragma unroll
            for (int mt = 0; mt < 2; mt++) {
                int row = wm * 32 + mt * 16 + g;
                int kb  = kk * 8 + t;
                a[mt][0] = As2[buf][ row      * PA + kb    ];
                a[mt][1] = As2[buf][(row + 8) * PA + kb    ];
                a[mt][2] = As2[buf][ row      * PA + kb + 4];
                a[mt][3] = As2[buf][(row + 8) * PA + kb + 4];
            }
#pragma unroll
            for (int nt = 0; nt < NT; nt++) {
                int col = wn * WN + nt * 8 + g;
                int kb  = kk * 8 + t;
                b[nt][0] = Bs2[buf][ kb      * PB + col];
                b[nt][1] = Bs2[buf][(kb + 4) * PB + col];
            }
#pragma unroll
            for (int mt = 0; mt < 2; mt++)
#pragma unroll
                for (int nt = 0; nt < NT; nt++) {
                    asm volatile(
                        "mma.sync.aligned.m16n8k16.row.col.f32.f16.f16.f32 "
                        "{%0,%1,%2,%3}, {%4,%5,%6,%7}, {%8,%9}, {%0,%1,%2,%3};"
                        : "+f"(acc[mt][nt][0]), "+f"(acc[mt][nt][1]),
                          "+f"(acc[mt][nt][2]), "+f"(acc[mt][nt][3])
                        : "r"(a[mt][0]), "r"(a[mt][1]), "r"(a[mt][2]), "r"(a[mt][3]),
                          "r"(b[nt][0]), "r"(b[nt][1]));
                }
        }
    };

    loadT(0);
    storeT(0);
    __syncthreads();

    int buf = 0;
    for (int k0 = 0; k0 < K; k0 += BK) {
        int kn = k0 + BK;
        if (kn < K) loadT(kn);        // LDG for next tile (latency hidden by MMA)
        doMMA(buf);
        if (kn < K) {
            storeT(buf ^ 1);
            __syncthreads();
            buf ^= 1;
        }
    }

#pragma unroll
    for (int mt = 0; mt < 2; mt++) {
        int row0 = bm + wm * 32 + mt * 16 + g;
#pragma unroll
        for (int nt = 0; nt < NT; nt++) {
            int col = bn + wn * WN + nt * 8 + t * 2;
            if (HALF_OUT) {
                __half* C = (__half*)Cv;
                if (row0 < M)
                    *(__half2*)(C + (size_t)row0 * N + col) =
                        __floats2half2_rn(acc[mt][nt][0], acc[mt][nt][1]);
                if (row0 + 8 < M)
                    *(__half2*)(C + (size_t)(row0 + 8) * N + col) =
                        __floats2half2_rn(acc[mt][nt][2], acc[mt][nt][3]);
            } else {
                float* C = (float*)Cv;
                if (row0 < M)
                    *(float2*)(C + (size_t)row0 * N + col) =
                        make_float2(acc[mt][nt][0], acc[mt][nt][1]);
                if (row0 + 8 < M)
                    *(float2*)(C + (size_t)(row0 + 8) * N + col) =
                        make_float2(acc[mt][nt][2], acc[mt][nt][3]);
            }
        }
    }
}

// ---------------------------------------------------------------------------
// CSR build: memset -> histogram(4/thr) -> single-block scan -> scatter(2/thr)
// ---------------------------------------------------------------------------
__global__ __launch_bounds__(256) void hist_dst(const int* __restrict__ dst,
                                                int* __restrict__ deg, int E) {
    int i = (blockIdx.x * 256 + threadIdx.x) * 4;
    if (i + 4 <= E) {
        int4 d = *(const int4*)(dst + i);
        atomicAdd(&deg[d.x], 1);
        atomicAdd(&deg[d.y], 1);
        atomicAdd(&deg[d.z], 1);
        atomicAdd(&deg[d.w], 1);
    } else {
        for (; i < E; i++) atomicAdd(&deg[dst[i]], 1);
    }
}

__global__ __launch_bounds__(1024) void scan_deg(const int* __restrict__ deg,
                                                 int* __restrict__ rowptr,
                                                 int* __restrict__ cursor, int n) {
    __shared__ int warp_sums[32];
    const int tid  = threadIdx.x;
    const int lane = tid & 31;
    const int wid  = tid >> 5;
    const int per  = (n + 1023) / 1024;
    const int start = tid * per;
    const int end   = min(start + per, n);

    int sum = 0;
    for (int i = start; i < end; i++) sum += deg[i];

    int v = sum;
#pragma unroll
    for (int o = 1; o < 32; o <<= 1) {
        int u = __shfl_up_sync(0xFFFFFFFFu, v, o);
        if (lane >= o) v += u;
    }
    if (lane == 31) warp_sums[wid] = v;
    __syncthreads();
    if (wid == 0) {
        int s = warp_sums[lane];
#pragma unroll
        for (int o = 1; o < 32; o <<= 1) {
            int u = __shfl_up_sync(0xFFFFFFFFu, s, o);
            if (lane >= o) s += u;
        }
        warp_sums[lane] = s;
    }
    __syncthreads();

    int run = v - sum + (wid ? warp_sums[wid - 1] : 0);
    for (int i = start; i < end; i++) {
        rowptr[i] = run;
        cursor[i] = run;
        run += deg[i];
    }
    if (start < n && end == n) rowptr[n] = run;
}

__global__ __launch_bounds__(256) void scatter_edges(const int* __restrict__ src,
                                                     const int* __restrict__ dst,
                                                     const float* __restrict__ w,
                                                     int* __restrict__ cursor,
                                                     int2* __restrict__ csr, int E) {
    int i = (blockIdx.x * 256 + threadIdx.x) * 2;
    if (i + 2 <= E) {
        int2   s2 = *(const int2*)(src + i);
        int2   d2 = *(const int2*)(dst + i);
        float2 w2 = *(const float2*)(w + i);
        int p0 = atomicAdd(&cursor[d2.x], 1);
        int p1 = atomicAdd(&cursor[d2.y], 1);
        csr[p0] = make_int2(s2.x, __float_as_int(w2.x));
        csr[p1] = make_int2(s2.y, __float_as_int(w2.y));
    } else {
        for (; i < E; i++) {
            int pos = atomicAdd(&cursor[dst[i]], 1);
            csr[pos] = make_int2(src[i], __float_as_int(w[i]));
        }
    }
}

// ---------------------------------------------------------------------------
// CSR SpMM, F=256: fp16 gather, fp32 accum, fused ReLU, fp16 output.
// One warp per dst row, 2-edge unroll.
// ---------------------------------------------------------------------------
__global__ __launch_bounds__(256) void spmm_csr_f256h_relu(const int* __restrict__ rowptr,
                                                           const int2* __restrict__ csr,
                                                           const __half* __restrict__ sup,
                                                           __half* __restrict__ out, int n) {
    int row  = (blockIdx.x * 256 + threadIdx.x) >> 5;
    int lane = threadIdx.x & 31;
    if (row >= n) return;
    int e   = rowptr[row];
    int end = rowptr[row + 1];

    float acc[8];
#pragma unroll
    for (int i = 0; i < 8; i++) acc[i] = 0.f;

    for (; e + 2 <= end; e += 2) {
        int2 sw0 = __ldg(&csr[e]);
        int2 sw1 = __ldg(&csr[e + 1]);
        float w0 = __int_as_float(sw0.y);
        float w1 = __int_as_float(sw1.y);
        uint4 v0 = ((const uint4*)(sup + (size_t)sw0.x * 256))[lane];
        uint4 v1 = ((const uint4*)(sup + (size_t)sw1.x * 256))[lane];
        const __half2* h0 = (const __half2*)&v0;
        const __half2* h1 = (const __half2*)&v1;
#pragma unroll
        for (int j = 0; j < 4; j++) {
            float2 f0 = __half22float2(h0[j]);
            float2 f1 = __half22float2(h1[j]);
            acc[2 * j]     += w0 * f0.x + w1 * f1.x;
            acc[2 * j + 1] += w0 * f0.y + w1 * f1.y;
        }
    }
    if (e < end) {
        int2 sw = __ldg(&csr[e]);
        float w = __int_as_float(sw.y);
        uint4 v = ((const uint4*)(sup + (size_t)sw.x * 256))[lane];
        const __half2* h = (const __half2*)&v;
#pragma unroll
        for (int j = 0; j < 4; j++) {
            float2 f = __half22float2(h[j]);
            acc[2 * j]     += w * f.x;
            acc[2 * j + 1] += w * f.y;
        }
    }

    uint4 o;
    o.x = pack_h2(fmaxf(acc[0], 0.f), fmaxf(acc[1], 0.f));
    o.y = pack_h2(fmaxf(acc[2], 0.f), fmaxf(acc[3], 0.f));
    o.z = pack_h2(fmaxf(acc[4], 0.f), fmaxf(acc[5], 0.f));
    o.w = pack_h2(fmaxf(acc[6], 0.f), fmaxf(acc[7], 0.f));
    *(uint4*)(out + (size_t)row * 256 + lane * 8) = o;
}

// ---------------------------------------------------------------------------
// CSR SpMM, F=64 (fp32), fused row-softmax: one warp per dst row.
// ---------------------------------------------------------------------------
__global__ __launch_bounds__(256) void spmm_csr_f64_softmax(const int* __restrict__ rowptr,
                                                            const int2* __restrict__ csr,
                                                            const float* __restrict__ sup,
                                                            float* __restrict__ out, int n) {
    int row  = (blockIdx.x * 256 + threadIdx.x) >> 5;
    int lane = threadIdx.x & 31;
    if (row >= n) return;
    int e   = rowptr[row];
    int end = rowptr[row + 1];

    float2 acc = make_float2(0.f, 0.f);

    for (; e + 2 <= end; e += 2) {
        int2 sw0 = __ldg(&csr[e]);
        int2 sw1 = __ldg(&csr[e + 1]);
        float w0 = __int_as_float(sw0.y);
        float w1 = __int_as_float(sw1.y);
        float2 v0 = ((const float2*)(sup + (size_t)sw0.x * 64))[lane];
        float2 v1 = ((const float2*)(sup + (size_t)sw1.x * 64))[lane];
        acc.x += w0 * v0.x + w1 * v1.x;
        acc.y += w0 * v0.y + w1 * v1.y;
    }
    if (e < end) {
        int2 sw = __ldg(&csr[e]);
        float w = __int_as_float(sw.y);
        float2 v = ((const float2*)(sup + (size_t)sw.x * 64))[lane];
        acc.x += w * v.x;
        acc.y += w * v.y;
    }

    float m = fmaxf(acc.x, acc.y);
#pragma unroll
    for (int o = 16; o; o >>= 1) m = fmaxf(m, __shfl_xor_sync(0xFFFFFFFFu, m, o));
    float ex = __expf(acc.x - m);
    float ey = __expf(acc.y - m);
    float s  = ex + ey;
#pragma unroll
    for (int o = 16; o; o >>= 1) s += __shfl_xor_sync(0xFFFFFFFFu, s, o);
    float inv = 1.f / s;
    ((float2*)(out + (size_t)row * 64))[lane] = make_float2(ex * inv, ey * inv);
}

// ---------------------------------------------------------------------------
extern "C" void kernel_launch(void* const* d_in, const int* in_sizes, int n_in,
                              void* d_out, int out_size) {
    const float* x  = (const float*)d_in[0];
    const int*   ei = (const int*)d_in[1];
    const float* ew = (const float*)d_in[2];
    const float* W1 = (const float*)d_in[3];
    const float* W2 = (const float*)d_in[4];
    float*       out = (float*)d_out;

    const int E = in_sizes[2];
    const int M = in_sizes[0] / IND;
    const int* src = ei;
    const int* dst = ei + E;

    __half *p_sup1, *p_h;
    float *p_sup2;
    int *p_deg, *p_rowptr, *p_cursor;
    int2 *p_csr;
    cudaGetSymbolAddress((void**)&p_sup1,   g_sup1);
    cudaGetSymbolAddress((void**)&p_h,      g_h);
    cudaGetSymbolAddress((void**)&p_sup2,   g_sup2);
    cudaGetSymbolAddress((void**)&p_deg,    g_deg);
    cudaGetSymbolAddress((void**)&p_rowptr, g_rowptr);
    cudaGetSymbolAddress((void**)&p_cursor, g_cursor);
    cudaGetSymbolAddress((void**)&p_csr,    g_csr);

    const int mt128 = (M + 127) / 128;

    // CSR build (dst-sorted adjacency, reused by both layers)
    cudaMemsetAsync(p_deg, 0, (size_t)M * sizeof(int));
    hist_dst<<<(E / 4 + 255) / 256, 256>>>(dst, p_deg, E);
    scan_deg<<<1, 1024>>>(p_deg, p_rowptr, p_cursor, M);
    scatter_edges<<<(E / 2 + 255) / 256, 256>>>(src, dst, ew, p_cursor, p_csr, E);

    // Layer 1: sup1 = fp16(x @ W1) ; h = fp16(relu(A @ sup1))
    gemm_f16_db<128, false, true><<<dim3(HIDD / 128, mt128), 256>>>(x, W1, p_sup1, M, HIDD, IND);
    spmm_csr_f256h_relu<<<(M * 32 + 255) / 256, 256>>>(p_rowptr, p_csr, p_sup1, p_h, M);

    // Layer 2: sup2 = h @ W2 (A already relu'd fp16) ; out = softmax(A @ sup2)
    gemm_f16_db<64, true, false><<<dim3(OUTD / 64, mt128), 256>>>(p_h, W2, p_sup2, M, OUTD, HIDD);
    spmm_csr_f64_softmax<<<(M * 32 + 255) / 256, 256>>>(p_rowptr, p_csr, p_sup2, out, M);
}

// round 11
// speedup vs baseline: 1.2534x; 1.0153x over previous
#include <cuda_runtime.h>
#include <cuda_fp16.h>
#include <cstdint>
#include <cstddef>
#include <cstring>

#define NN   100000
#define IND  512
#define HIDD 256
#define OUTD 64
#define NEDGE_MAX 3400000

// Scratch (device globals: allocation-free, graph-capture safe). ~160 MB.
__device__ __half g_sup1[(size_t)NN * HIDD]; // fp16(x @ W1)
__device__ __half g_h   [(size_t)NN * HIDD]; // fp16(relu(spmm1))
__device__ float  g_sup2[(size_t)NN * OUTD]; // relu(h) @ W2
__device__ int    g_deg   [NN];
__device__ int    g_rowptr[NN + 1];
__device__ int    g_cursor[NN];
__device__ int2   g_csr   [NEDGE_MAX];       // {src, w-bits} sorted by dst

__device__ __forceinline__ unsigned h2_as_u32(__half2 h) {
    unsigned u;
    *reinterpret_cast<__half2*>(&u) = h;
    return u;
}
__device__ __forceinline__ unsigned pack_h2(float lo, float hi) {
    return h2_as_u32(__floats2half2_rn(lo, hi));
}

// ---------------------------------------------------------------------------
// FP16 tensor-core GEMM, double-buffered static SMEM + register prefetch,
// A-fragments via ldmatrix.x4. C[M,N] = A[M,K] @ B[K,N] row-major.
// BM=128, BK=32, 256 thr = 8 warps (4M x 2N), warp tile 32 x (BN/2),
// mma.sync.m16n8k16.f32.f16.f16.f32; one __syncthreads per K-iter.
// ---------------------------------------------------------------------------
template <int BN, bool A_HALF, bool HALF_OUT>
__global__ __launch_bounds__(256, 2) void gemm_f16_db(const void* __restrict__ Av,
                                                      const float* __restrict__ B,
                                                      void* __restrict__ Cv,
                                                      int M, int N, int K) {
    constexpr int BM = 128, BK = 32;
    constexpr int PA = 20;        // u32 words per A row (16 half2 + 4 pad)
    constexpr int PB = BN + 8;    // u32 words per B k2-row
    constexpr int WN = BN / 2;
    constexpr int NT = WN / 8;
    constexpr int BI = (16 * BN / 4) / 256;   // B fill items per thread (2 or 1)

    __shared__ __align__(16) unsigned As2[2][BM * PA];
    __shared__ __align__(16) unsigned Bs2[2][(BK / 2) * PB];

    const int tid  = threadIdx.x;
    const int warp = tid >> 5;
    const int lane = tid & 31;
    const int g    = lane >> 2;
    const int t    = lane & 3;
    const int wm   = warp & 3;
    const int wn   = warp >> 2;
    const int bm   = blockIdx.y * BM;
    const int bn   = blockIdx.x * BN;

    const float*  Af = (const float*)Av;
    const __half* Ah = (const __half*)Av;

    float acc[2][NT][4];
#pragma unroll
    for (int mt = 0; mt < 2; mt++)
#pragma unroll
        for (int nt = 0; nt < NT; nt++)
#pragma unroll
            for (int i = 0; i < 4; i++) acc[mt][nt][i] = 0.f;

    float4 pa[4];        // A prefetch (A_HALF uses pa[0..1] as uint4 bits)
    float4 pb[BI][2];    // B prefetch

    // ldmatrix lane-address offset within an A buffer (in u32 words):
    //   row = wm*32 + mt*16 + (lane & 15); matrix pair select = (lane >> 4)*4
    const int lm_off = (wm * 32 + (lane & 15)) * PA + (lane >> 4) * 4;

    auto loadT = [&](int k0) {
        if (!A_HALF) {
#pragma unroll
            for (int i = 0; i < 4; i++) {
                int idx = tid + i * 256;
                int r   = idx >> 3;
                int c4  = idx & 7;
                int gr  = bm + r;
                float4 v = make_float4(0.f, 0.f, 0.f, 0.f);
                if (gr < M) v = *(const float4*)(Af + (size_t)gr * K + k0 + c4 * 4);
                pa[i] = v;
            }
        } else {
#pragma unroll
            for (int i = 0; i < 2; i++) {
                int idx = tid + i * 256;
                int r   = idx >> 2;
                int c   = idx & 3;
                int gr  = bm + r;
                uint4 v = make_uint4(0u, 0u, 0u, 0u);
                if (gr < M) v = *(const uint4*)(Ah + (size_t)gr * K + k0 + c * 8);
                memcpy(&pa[i * 2], &v, 16);
            }
        }
#pragma unroll
        for (int i = 0; i < BI; i++) {
            int idx = tid + i * 256;
            int k2  = idx / (BN / 4);
            int n4  = idx % (BN / 4);
            const float* b0 = B + (size_t)(k0 + 2 * k2) * N + bn + n4 * 4;
            pb[i][0] = *(const float4*)b0;
            pb[i][1] = *(const float4*)(b0 + N);
        }
    };
    auto storeT = [&](int buf) {
        if (!A_HALF) {
#pragma unroll
            for (int i = 0; i < 4; i++) {
                int idx = tid + i * 256;
                int r   = idx >> 3;
                int c4  = idx & 7;
                uint2 p;
                p.x = pack_h2(pa[i].x, pa[i].y);
                p.y = pack_h2(pa[i].z, pa[i].w);
                *(uint2*)&As2[buf][r * PA + c4 * 2] = p;
            }
        } else {
#pragma unroll
            for (int i = 0; i < 2; i++) {
                int idx = tid + i * 256;
                int r   = idx >> 2;
                int c   = idx & 3;
                uint4 v;
                memcpy(&v, &pa[i * 2], 16);
                *(uint4*)&As2[buf][r * PA + c * 4] = v;
            }
        }
#pragma unroll
        for (int i = 0; i < BI; i++) {
            int idx = tid + i * 256;
            int k2  = idx / (BN / 4);
            int n4  = idx % (BN / 4);
            uint4 p;
            p.x = pack_h2(pb[i][0].x, pb[i][1].x);
            p.y = pack_h2(pb[i][0].y, pb[i][1].y);
            p.z = pack_h2(pb[i][0].z, pb[i][1].z);
            p.w = pack_h2(pb[i][0].w, pb[i][1].w);
            *(uint4*)&Bs2[buf][k2 * PB + n4 * 4] = p;
        }
    };
    auto doMMA = [&](int buf) {
        unsigned a_base = (unsigned)__cvta_generic_to_shared(&As2[buf][lm_off]);
#pragma unroll
        for (int kk = 0; kk < 2; kk++) {
            unsigned a[2][4], b[NT][2];
#pragma unroll
            for (int mt = 0; mt < 2; mt++) {
                // matrices: {rows+0..7, rows+8..15} x {k-half 0, k-half 1}
                unsigned addr = a_base + (mt * 16 * PA + kk * 8) * 4;
                asm volatile(
                    "ldmatrix.sync.aligned.m8n8.x4.shared.b16 {%0,%1,%2,%3}, [%4];"
                    : "=r"(a[mt][0]), "=r"(a[mt][1]), "=r"(a[mt][2]), "=r"(a[mt][3])
                    : "r"(addr));
            }
#pragma unroll
            for (int nt = 0; nt < NT; nt++) {
                int col = wn * WN + nt * 8 + g;
                int kb  = kk * 8 + t;
                b[nt][0] = Bs2[buf][ kb      * PB + col];
                b[nt][1] = Bs2[buf][(kb + 4) * PB + col];
            }
#pragma unroll
            for (int mt = 0; mt < 2; mt++)
#pragma unroll
                for (int nt = 0; nt < NT; nt++) {
                    asm volatile(
                        "mma.sync.aligned.m16n8k16.row.col.f32.f16.f16.f32 "
                        "{%0,%1,%2,%3}, {%4,%5,%6,%7}, {%8,%9}, {%0,%1,%2,%3};"
                        : "+f"(acc[mt][nt][0]), "+f"(acc[mt][nt][1]),
                          "+f"(acc[mt][nt][2]), "+f"(acc[mt][nt][3])
                        : "r"(a[mt][0]), "r"(a[mt][1]), "r"(a[mt][2]), "r"(a[mt][3]),
                          "r"(b[nt][0]), "r"(b[nt][1]));
                }
        }
    };

    loadT(0);
    storeT(0);
    __syncthreads();

    int buf = 0;
    for (int k0 = 0; k0 < K; k0 += BK) {
        int kn = k0 + BK;
        if (kn < K) loadT(kn);
        doMMA(buf);
        if (kn < K) {
            storeT(buf ^ 1);
            __syncthreads();
            buf ^= 1;
        }
    }

#pragma unroll
    for (int mt = 0; mt < 2; mt++) {
        int row0 = bm + wm * 32 + mt * 16 + g;
#pragma unroll
        for (int nt = 0; nt < NT; nt++) {
            int col = bn + wn * WN + nt * 8 + t * 2;
            if (HALF_OUT) {
                __half* C = (__half*)Cv;
                if (row0 < M)
                    *(__half2*)(C + (size_t)row0 * N + col) =
                        __floats2half2_rn(acc[mt][nt][0], acc[mt][nt][1]);
                if (row0 + 8 < M)
                    *(__half2*)(C + (size_t)(row0 + 8) * N + col) =
                        __floats2half2_rn(acc[mt][nt][2], acc[mt][nt][3]);
            } else {
                float* C = (float*)Cv;
                if (row0 < M)
                    *(float2*)(C + (size_t)row0 * N + col) =
                        make_float2(acc[mt][nt][0], acc[mt][nt][1]);
                if (row0 + 8 < M)
                    *(float2*)(C + (size_t)(row0 + 8) * N + col) =
                        make_float2(acc[mt][nt][2], acc[mt][nt][3]);
            }
        }
    }
}

// ---------------------------------------------------------------------------
// CSR build: memset -> histogram(4/thr) -> single-block scan -> scatter(2/thr)
// ---------------------------------------------------------------------------
__global__ __launch_bounds__(256) void hist_dst(const int* __restrict__ dst,
                                                int* __restrict__ deg, int E) {
    int i = (blockIdx.x * 256 + threadIdx.x) * 4;
    if (i + 4 <= E) {
        int4 d = *(const int4*)(dst + i);
        atomicAdd(&deg[d.x], 1);
        atomicAdd(&deg[d.y], 1);
        atomicAdd(&deg[d.z], 1);
        atomicAdd(&deg[d.w], 1);
    } else {
        for (; i < E; i++) atomicAdd(&deg[dst[i]], 1);
    }
}

__global__ __launch_bounds__(1024) void scan_deg(const int* __restrict__ deg,
                                                 int* __restrict__ rowptr,
                                                 int* __restrict__ cursor, int n) {
    __shared__ int warp_sums[32];
    const int tid  = threadIdx.x;
    const int lane = tid & 31;
    const int wid  = tid >> 5;
    const int per  = (n + 1023) / 1024;
    const int start = tid * per;
    const int end   = min(start + per, n);

    int sum = 0;
    for (int i = start; i < end; i++) sum += deg[i];

    int v = sum;
#pragma unroll
    for (int o = 1; o < 32; o <<= 1) {
        int u = __shfl_up_sync(0xFFFFFFFFu, v, o);
        if (lane >= o) v += u;
    }
    if (lane == 31) warp_sums[wid] = v;
    __syncthreads();
    if (wid == 0) {
        int s = warp_sums[lane];
#pragma unroll
        for (int o = 1; o < 32; o <<= 1) {
            int u = __shfl_up_sync(0xFFFFFFFFu, s, o);
            if (lane >= o) s += u;
        }
        warp_sums[lane] = s;
    }
    __syncthreads();

    int run = v - sum + (wid ? warp_sums[wid - 1] : 0);
    for (int i = start; i < end; i++) {
        rowptr[i] = run;
        cursor[i] = run;
        run += deg[i];
    }
    if (start < n && end == n) rowptr[n] = run;
}

__global__ __launch_bounds__(256) void scatter_edges(const int* __restrict__ src,
                                                     const int* __restrict__ dst,
                                                     const float* __restrict__ w,
                                                     int* __restrict__ cursor,
                                                     int2* __restrict__ csr, int E) {
    int i = (blockIdx.x * 256 + threadIdx.x) * 2;
    if (i + 2 <= E) {
        int2   s2 = *(const int2*)(src + i);
        int2   d2 = *(const int2*)(dst + i);
        float2 w2 = *(const float2*)(w + i);
        int p0 = atomicAdd(&cursor[d2.x], 1);
        int p1 = atomicAdd(&cursor[d2.y], 1);
        csr[p0] = make_int2(s2.x, __float_as_int(w2.x));
        csr[p1] = make_int2(s2.y, __float_as_int(w2.y));
    } else {
        for (; i < E; i++) {
            int pos = atomicAdd(&cursor[dst[i]], 1);
            csr[pos] = make_int2(src[i], __float_as_int(w[i]));
        }
    }
}

// ---------------------------------------------------------------------------
// CSR SpMM, F=256: fp16 gather, fp32 accum, fused ReLU, fp16 output.
// ---------------------------------------------------------------------------
__global__ __launch_bounds__(256) void spmm_csr_f256h_relu(const int* __restrict__ rowptr,
                                                           const int2* __restrict__ csr,
                                                           const __half* __restrict__ sup,
                                                           __half* __restrict__ out, int n) {
    int row  = (blockIdx.x * 256 + threadIdx.x) >> 5;
    int lane = threadIdx.x & 31;
    if (row >= n) return;
    int e   = rowptr[row];
    int end = rowptr[row + 1];

    float acc[8];
#pragma unroll
    for (int i = 0; i < 8; i++) acc[i] = 0.f;

    for (; e + 2 <= end; e += 2) {
        int2 sw0 = __ldg(&csr[e]);
        int2 sw1 = __ldg(&csr[e + 1]);
        float w0 = __int_as_float(sw0.y);
        float w1 = __int_as_float(sw1.y);
        uint4 v0 = ((const uint4*)(sup + (size_t)sw0.x * 256))[lane];
        uint4 v1 = ((const uint4*)(sup + (size_t)sw1.x * 256))[lane];
        const __half2* h0 = (const __half2*)&v0;
        const __half2* h1 = (const __half2*)&v1;
#pragma unroll
        for (int j = 0; j < 4; j++) {
            float2 f0 = __half22float2(h0[j]);
            float2 f1 = __half22float2(h1[j]);
            acc[2 * j]     += w0 * f0.x + w1 * f1.x;
            acc[2 * j + 1] += w0 * f0.y + w1 * f1.y;
        }
    }
    if (e < end) {
        int2 sw = __ldg(&csr[e]);
        float w = __int_as_float(sw.y);
        uint4 v = ((const uint4*)(sup + (size_t)sw.x * 256))[lane];
        const __half2* h = (const __half2*)&v;
#pragma unroll
        for (int j = 0; j < 4; j++) {
            float2 f = __half22float2(h[j]);
            acc[2 * j]     += w * f.x;
            acc[2 * j + 1] += w * f.y;
        }
    }

    uint4 o;
    o.x = pack_h2(fmaxf(acc[0], 0.f), fmaxf(acc[1], 0.f));
    o.y = pack_h2(fmaxf(acc[2], 0.f), fmaxf(acc[3], 0.f));
    o.z = pack_h2(fmaxf(acc[4], 0.f), fmaxf(acc[5], 0.f));
    o.w = pack_h2(fmaxf(acc[6], 0.f), fmaxf(acc[7], 0.f));
    *(uint4*)(out + (size_t)row * 256 + lane * 8) = o;
}

// ---------------------------------------------------------------------------
// CSR SpMM, F=64 (fp32), fused row-softmax: one warp per dst row.
// ---------------------------------------------------------------------------
__global__ __launch_bounds__(256) void spmm_csr_f64_softmax(const int* __restrict__ rowptr,
                                                            const int2* __restrict__ csr,
                                                            const float* __restrict__ sup,
                                                            float* __restrict__ out, int n) {
    int row  = (blockIdx.x * 256 + threadIdx.x) >> 5;
    int lane = threadIdx.x & 31;
    if (row >= n) return;
    int e   = rowptr[row];
    int end = rowptr[row + 1];

    float2 acc = make_float2(0.f, 0.f);

    for (; e + 2 <= end; e += 2) {
        int2 sw0 = __ldg(&csr[e]);
        int2 sw1 = __ldg(&csr[e + 1]);
        float w0 = __int_as_float(sw0.y);
        float w1 = __int_as_float(sw1.y);
        float2 v0 = ((const float2*)(sup + (size_t)sw0.x * 64))[lane];
        float2 v1 = ((const float2*)(sup + (size_t)sw1.x * 64))[lane];
        acc.x += w0 * v0.x + w1 * v1.x;
        acc.y += w0 * v0.y + w1 * v1.y;
    }
    if (e < end) {
        int2 sw = __ldg(&csr[e]);
        float w = __int_as_float(sw.y);
        float2 v = ((const float2*)(sup + (size_t)sw.x * 64))[lane];
        acc.x += w * v.x;
        acc.y += w * v.y;
    }

    float m = fmaxf(acc.x, acc.y);
#pragma unroll
    for (int o = 16; o; o >>= 1) m = fmaxf(m, __shfl_xor_sync(0xFFFFFFFFu, m, o));
    float ex = __expf(acc.x - m);
    float ey = __expf(acc.y - m);
    float s  = ex + ey;
#pragma unroll
    for (int o = 16; o; o >>= 1) s += __shfl_xor_sync(0xFFFFFFFFu, s, o);
    float inv = 1.f / s;
    ((float2*)(out + (size_t)row * 64))[lane] = make_float2(ex * inv, ey * inv);
}

// ---------------------------------------------------------------------------
extern "C" void kernel_launch(void* const* d_in, const int* in_sizes, int n_in,
                              void* d_out, int out_size) {
    const float* x  = (const float*)d_in[0];
    const int*   ei = (const int*)d_in[1];
    const float* ew = (const float*)d_in[2];
    const float* W1 = (const float*)d_in[3];
    const float* W2 = (const float*)d_in[4];
    float*       out = (float*)d_out;

    const int E = in_sizes[2];
    const int M = in_sizes[0] / IND;
    const int* src = ei;
    const int* dst = ei + E;

    __half *p_sup1, *p_h;
    float *p_sup2;
    int *p_deg, *p_rowptr, *p_cursor;
    int2 *p_csr;
    cudaGetSymbolAddress((void**)&p_sup1,   g_sup1);
    cudaGetSymbolAddress((void**)&p_h,      g_h);
    cudaGetSymbolAddress((void**)&p_sup2,   g_sup2);
    cudaGetSymbolAddress((void**)&p_deg,    g_deg);
    cudaGetSymbolAddress((void**)&p_rowptr, g_rowptr);
    cudaGetSymbolAddress((void**)&p_cursor, g_cursor);
    cudaGetSymbolAddress((void**)&p_csr,    g_csr);

    const int mt128 = (M + 127) / 128;

    // CSR build (dst-sorted adjacency, reused by both layers)
    cudaMemsetAsync(p_deg, 0, (size_t)M * sizeof(int));
    hist_dst<<<(E / 4 + 255) / 256, 256>>>(dst, p_deg, E);
    scan_deg<<<1, 1024>>>(p_deg, p_rowptr, p_cursor, M);
    scatter_edges<<<(E / 2 + 255) / 256, 256>>>(src, dst, ew, p_cursor, p_csr, E);

    // Layer 1: sup1 = fp16(x @ W1) ; h = fp16(relu(A @ sup1))
    gemm_f16_db<128, false, true><<<dim3(HIDD / 128, mt128), 256>>>(x, W1, p_sup1, M, HIDD, IND);
    spmm_csr_f256h_relu<<<(M * 32 + 255) / 256, 256>>>(p_rowptr, p_csr, p_sup1, p_h, M);

    // Layer 2: sup2 = h @ W2 ; out = softmax(A @ sup2)
    gemm_f16_db<64, true, false><<<dim3(OUTD / 64, mt128), 256>>>(p_h, W2, p_sup2, M, OUTD, HIDD);
    spmm_csr_f64_softmax<<<(M * 32 + 255) / 256, 256>>>(p_rowptr, p_csr, p_sup2, out, M);
}